// round 8
// baseline (speedup 1.0000x reference)
#include <cuda_runtime.h>
#include <cstdint>

#define NUM_BINS 32
#define MAXK     4
#define MAXU     100352
#define NMAXV    (2*MAXU)
#define NPAD     (NMAXV + 64)

typedef unsigned long long u64;

__device__ int   g_cnt[MAXU];
__device__ int4  g_list[MAXU];                   // packed (voxel<<5 | bin)
__device__ float g_xT[(size_t)64 * NPAD];        // transposed MLP output [c][v]
__device__ float g_xemp[64];                     // MLP(0) vector

// ---------------- packed f32x2 helpers -------------------------------------
__device__ __forceinline__ u64 pk2(float lo, float hi) {
    u64 r; asm("mov.b64 %0,{%1,%2};" : "=l"(r) : "f"(lo), "f"(hi)); return r;
}
__device__ __forceinline__ u64 dup2(float v) { return pk2(v, v); }
__device__ __forceinline__ void fma2(u64 &d, u64 a, u64 b) {
    asm("fma.rn.f32x2 %0,%1,%2,%0;" : "+l"(d) : "l"(a), "l"(b));
}
__device__ __forceinline__ float2 unpk(u64 v) {
    float2 r; asm("mov.b64 {%0,%1},%2;" : "=f"(r.x), "=f"(r.y) : "l"(v)); return r;
}
union F4U { float4 f; u64 u[2]; };

__device__ __forceinline__ float sigm(float x) {
    return __fdividef(1.f, 1.f + __expf(-x));
}

// ---------------------------------------------------------------- scatter ---
__global__ void scatter_kernel(const int* __restrict__ unq_inv,
                               const int* __restrict__ coords, int N) {
    int i = blockIdx.x * blockDim.x + threadIdx.x;
    if (i >= N) return;
    int p = unq_inv[i];
    int b = coords[4 * i + 1];
    int k = atomicAdd(&g_cnt[p], 1);
    if (k < MAXK) ((int*)g_list)[p * 4 + k] = (i << 5) | (b & 31);
}

// ------------------------------------------------------------------- mask ---
__global__ void mask_kernel(const int* __restrict__ cnt, float* __restrict__ out,
                            long long base, int n) {
    int i = blockIdx.x * blockDim.x + threadIdx.x;
    if (i < n) out[base + i] = (cnt[i] >= 2) ? 1.0f : 0.0f;
}

// ------------------------------------------------------------------- xemp ---
__global__ void xemp_kernel(const float* __restrict__ b1,
                            const float* __restrict__ W2,
                            const float* __restrict__ b2) {
    int c = threadIdx.x;   // 64 threads
    float acc = b2[c];
#pragma unroll
    for (int j = 0; j < 32; j++)
        acc = fmaf(fmaxf(b1[j], 0.f), W2[j * 64 + c], acc);
    g_xemp[c] = acc;
}

// ---------------------------------------------------- kernel A: MLP (tiled) --
__global__ __launch_bounds__(256)
void mlp2_kernel(const float* __restrict__ vf,
                 const float* __restrict__ W1, const float* __restrict__ b1,
                 const float* __restrict__ W2, const float* __restrict__ b2,
                 int N) {
    __shared__ __align__(16) float W1s[5][32];
    __shared__ __align__(16) float b1s[32];
    __shared__ __align__(16) float W2s[32][64];
    __shared__ __align__(16) float b2s[64];
    __shared__ __align__(16) float h_sh[32][68];
    __shared__ __align__(16) float x_sh[64][65];

    const int tid  = threadIdx.x;
    const int cp   = tid & 31;
    const int slot = tid >> 5;
    const int v0   = blockIdx.x * 64;

    for (int i = tid; i < 160; i += 256) W1s[i / 32][i % 32] = W1[i];
    if (tid < 32) b1s[tid] = b1[tid];
    for (int i = tid; i < 2048; i += 256) W2s[i >> 6][i & 63] = W2[i];
    if (tid < 64) b2s[tid] = b2[tid];
    __syncthreads();

    // ---- phase A: hidden ----
    {
        int v = tid & 63, qr = tid >> 6;
        int gv = v0 + v;
        float f[5];
        bool ok = gv < N;
#pragma unroll
        for (int i = 0; i < 5; i++) f[i] = ok ? vf[(size_t)gv * 5 + i] : 0.f;
        u64 acc[4];
#pragma unroll
        for (int t = 0; t < 4; t++) acc[t] = *(const u64*)&b1s[qr * 8 + 2 * t];
#pragma unroll
        for (int i = 0; i < 5; i++) {
            u64 fd = dup2(f[i]);
#pragma unroll
            for (int t = 0; t < 4; t++)
                fma2(acc[t], fd, *(const u64*)&W1s[i][qr * 8 + 2 * t]);
        }
#pragma unroll
        for (int t = 0; t < 4; t++) {
            float2 h = unpk(acc[t]);
            h_sh[qr * 8 + 2 * t][v]     = fmaxf(h.x, 0.f);
            h_sh[qr * 8 + 2 * t + 1][v] = fmaxf(h.y, 0.f);
        }
    }
    __syncthreads();

    // ---- phase B: layer 2 ----
    {
        const int vb = slot * 8;
        float2 b2p = *(const float2*)&b2s[2 * cp];
        u64 accA[4], accB[4];
#pragma unroll
        for (int t = 0; t < 4; t++) { accA[t] = dup2(b2p.x); accB[t] = dup2(b2p.y); }
#pragma unroll 4
        for (int j = 0; j < 32; j++) {
            F4U A, B;
            A.f = *(const float4*)&h_sh[j][vb];
            B.f = *(const float4*)&h_sh[j][vb + 4];
            float2 w = *(const float2*)&W2s[j][2 * cp];
            u64 d0 = dup2(w.x), d1 = dup2(w.y);
            fma2(accA[0], A.u[0], d0); fma2(accA[1], A.u[1], d0);
            fma2(accA[2], B.u[0], d0); fma2(accA[3], B.u[1], d0);
            fma2(accB[0], A.u[0], d1); fma2(accB[1], A.u[1], d1);
            fma2(accB[2], B.u[0], d1); fma2(accB[3], B.u[1], d1);
        }
#pragma unroll
        for (int t = 0; t < 4; t++) {
            float2 a = unpk(accA[t]);
            float2 b = unpk(accB[t]);
            x_sh[vb + 2 * t][2 * cp]         = a.x;
            x_sh[vb + 2 * t + 1][2 * cp]     = a.y;
            x_sh[vb + 2 * t][2 * cp + 1]     = b.x;
            x_sh[vb + 2 * t + 1][2 * cp + 1] = b.y;
        }
    }
    __syncthreads();

    for (int idx = tid; idx < 64 * 64; idx += 256) {
        int c = idx >> 6, v = idx & 63;
        if (v0 + v < N) g_xT[(size_t)c * NPAD + v0 + v] = x_sh[v][c];
    }
}

// -------------------------------------------------- kernel B: attention -----
// thread = pillar (pillar3 structure). att cached in REGISTERS across phases;
// quarter-sized output staging; high occupancy.
__global__ __launch_bounds__(128, 12)
void pillar5_kernel(const int* __restrict__ unq_cnt,
                    const float* __restrict__ Wc1, const float* __restrict__ bc1,
                    const float* __restrict__ Wc2, const float* __restrict__ bc2,
                    const float* __restrict__ Wsp, const float* __restrict__ bsp,
                    float* __restrict__ out, int U) {
    __shared__ __align__(16) float Wc1s[64 * 16];   // [c][j]
    __shared__ __align__(16) u64   Wc2P[32 * 16];   // [q][j] packed ch-pairs
    __shared__ __align__(16) float xemps[64];
    __shared__ __align__(16) u64   xem2[32];        // packed xemp pairs
    __shared__ float bc1s[16];
    __shared__ __align__(16) u64   bc22p[32];       // 2*bc2 packed pairs
    __shared__ __align__(16) u64   Amx[32];         // conv bg coeffs per bin
    __shared__ __align__(16) u64   wmx[7];          // packed (wm[t], wx[t])
    __shared__ __align__(16) u64   oh[8][131];      // quarter-output staging

    const int tid = threadIdx.x;
    for (int i = tid; i < 1024; i += 128) Wc1s[i] = Wc1[i];
    for (int i = tid; i < 512; i += 128) {
        int q = i >> 4, j = i & 15;
        Wc2P[q * 16 + j] = pk2(Wc2[j * 64 + 2 * q], Wc2[j * 64 + 2 * q + 1]);
    }
    if (tid < 64) xemps[tid] = g_xemp[tid];
    if (tid < 32) {
        xem2[tid]  = pk2(g_xemp[2 * tid], g_xemp[2 * tid + 1]);
        bc22p[tid] = pk2(2.f * bc2[2 * tid], 2.f * bc2[2 * tid + 1]);
        float am = 0.f, ax = 0.f;
#pragma unroll
        for (int t = 0; t < 7; t++) {
            int i2 = tid + t - 3;
            if (i2 >= 0 && i2 < 32) { am += Wsp[t]; ax += Wsp[7 + t]; }
        }
        Amx[tid] = pk2(am, ax);
    }
    if (tid < 16) bc1s[tid] = bc1[tid];
    if (tid < 7)  wmx[tid] = pk2(Wsp[tid], Wsp[7 + tid]);
    __syncthreads();

    const float bspv = bsp[0];
    const float NEG = __int_as_float(0xff800000);
    const int pbase = blockIdx.x * 128;
    const int p = pbase + tid;
    const bool active = p < U;

    int K = 0;
    int4 e = make_int4(0, 0, 0, 0);
    if (active) {
        K = unq_cnt[p];
        K = (K < 0) ? 0 : ((K > MAXK) ? MAXK : K);
        e = g_list[p];
    }
    int vs_[4] = { e.x >> 5, e.y >> 5, e.z >> 5, e.w >> 5 };
    int bs_[4] = { e.x & 31, e.y & 31, e.z & 31, e.w & 31 };
#pragma unroll
    for (int k = 0; k < 4; k++) if (k >= K) { bs_[k] = -1000; vs_[k] = 0; }
    const float fK = (float)(NUM_BINS - K);

    // ---- phase 1: avg/max per channel -> catt hidden partials -------------
    u64 ap[8], aq[8];
#pragma unroll
    for (int j = 0; j < 8; j++) { ap[j] = 0ull; aq[j] = 0ull; }
    {
        const float* xc = g_xT;
#pragma unroll 4
        for (int c = 0; c < 64; c++) {
            float xe = xemps[c];
            float s = 0.f, mx = xe;
#pragma unroll
            for (int k = 0; k < 4; k++) if (k < K) {
                float xv = xc[vs_[k]];
                s += xv; mx = fmaxf(mx, xv);
            }
            float av = (s + fK * xe) * 0.03125f;
            u64 ad = dup2(av), md = dup2(mx);
            const ulonglong2* wr = (const ulonglong2*)&Wc1s[c * 16];
#pragma unroll
            for (int h = 0; h < 4; h++) {
                ulonglong2 w = wr[h];
                fma2(ap[2 * h],     ad, w.x);
                fma2(ap[2 * h + 1], ad, w.y);
                fma2(aq[2 * h],     md, w.x);
                fma2(aq[2 * h + 1], md, w.y);
            }
            xc += NPAD;
        }
    }

    // ---- catt gate vector, packed dups -----------------------------------
    u64 gd[16];
#pragma unroll
    for (int jp = 0; jp < 8; jp++) {
        float2 pp = unpk(ap[jp]);
        float2 qq = unpk(aq[jp]);
        float g0 = fmaxf(pp.x + bc1s[2 * jp], 0.f)     + fmaxf(qq.x + bc1s[2 * jp], 0.f);
        float g1 = fmaxf(pp.y + bc1s[2 * jp + 1], 0.f) + fmaxf(qq.y + bc1s[2 * jp + 1], 0.f);
        gd[2 * jp]     = dup2(g0);
        gd[2 * jp + 1] = dup2(g1);
    }

    // ---- phase 2: channel attention (kept in REGISTERS) + bin statistics --
    u64 att_r[32];
    float ssum[4] = {0.f, 0.f, 0.f, 0.f};
    float smax4[4] = {NEG, NEG, NEG, NEG};
    float sesum = 0.f, semax = NEG;
    {
        const float* x0 = g_xT;
        const float* x1 = g_xT + NPAD;
#pragma unroll
        for (int q = 0; q < 32; q++) {
            u64 acc = bc22p[q];
            const ulonglong2* w2 = (const ulonglong2*)&Wc2P[q * 16];
#pragma unroll
            for (int h = 0; h < 8; h++) {
                ulonglong2 w = w2[h];
                fma2(acc, gd[2 * h],     w.x);
                fma2(acc, gd[2 * h + 1], w.y);
            }
            float2 A = unpk(acc);
            float a0 = sigm(A.x), a1 = sigm(A.y);
            att_r[q] = pk2(a0, a1);
            float2 xe = unpk(xem2[q]);
            float y0 = a0 * xe.x, y1 = a1 * xe.y;
            sesum += y0 + y1;
            semax = fmaxf(semax, fmaxf(y0, y1));
#pragma unroll
            for (int k = 0; k < 4; k++) if (k < K) {
                float z0 = a0 * x0[vs_[k]];
                float z1 = a1 * x1[vs_[k]];
                ssum[k] += z0 + z1;
                smax4[k] = fmaxf(smax4[k], fmaxf(z0, z1));
            }
            x0 += 2 * NPAD;
            x1 += 2 * NPAD;
        }
    }

    // ---- bin attention: bg + sparse corrections --------------------------
    const float se_m = sesum * (1.f / 64.f);
    const float se_x = semax;
    const u64 semx = pk2(se_m, se_x);
    u64 dk2[4];
#pragma unroll
    for (int k = 0; k < 4; k++)
        dk2[k] = pk2(ssum[k] * (1.f / 64.f) - se_m, smax4[k] - se_x);

    float argk[4] = {0.f, 0.f, 0.f, 0.f};
    float emax = NEG, emin = -NEG;
#pragma unroll
    for (int b = 0; b < 32; b++) {
        u64 a2 = pk2(bspv, 0.f);
        fma2(a2, semx, Amx[b]);
        bool occ = false;
        bool hit[4];
#pragma unroll
        for (int k = 0; k < 4; k++) {
            int d = bs_[k] - b;
            if ((unsigned)(d + 3) <= 6u) fma2(a2, dk2[k], wmx[d + 3]);
            hit[k] = (d == 0);
            occ |= hit[k];
        }
        float2 av = unpk(a2);
        float a = av.x + av.y;
#pragma unroll
        for (int k = 0; k < 4; k++) argk[k] = hit[k] ? a : argk[k];
        emax = occ ? emax : fmaxf(emax, a);
        emin = occ ? emin : fminf(emin, a);
    }
    float sigk[4];
#pragma unroll
    for (int k = 0; k < 4; k++) sigk[k] = sigm(argk[k]);
    const float sigeP = sigm(emax);    // y_empty >= 0
    const float sigeN = sigm(emin);    // y_empty <  0

    // ---- phase 3: final max over bins, att from regs, 4 staged quarters --
#pragma unroll
    for (int quarter = 0; quarter < 4; quarter++) {
        {
            const float* x0 = g_xT + (size_t)(quarter * 16) * NPAD;
            const float* x1 = x0 + NPAD;
#pragma unroll
            for (int qq = 0; qq < 8; qq++) {
                int q = quarter * 8 + qq;
                float2 A = unpk(att_r[q]);
                float2 xe = unpk(xem2[q]);
                float M0 = xe.x * ((xe.x >= 0.f) ? sigeP : sigeN);
                float M1 = xe.y * ((xe.y >= 0.f) ? sigeP : sigeN);
#pragma unroll
                for (int k = 0; k < 4; k++) if (k < K) {
                    M0 = fmaxf(M0, x0[vs_[k]] * sigk[k]);
                    M1 = fmaxf(M1, x1[vs_[k]] * sigk[k]);
                }
                oh[qq][tid] = pk2(A.x * M0, A.y * M1);
                x0 += 2 * NPAD;
                x1 += 2 * NPAD;
            }
        }
        __syncthreads();
        // coalesced u64 writeout of this 16-channel quarter
        for (int idx = tid; idx < 128 * 8; idx += 128) {
            int pl = idx >> 3, qq = idx & 7;
            int pg = pbase + pl;
            if (pg < U)
                *(u64*)(out + (size_t)pg * 64 + quarter * 16 + 2 * qq) = oh[qq][pl];
        }
        __syncthreads();
    }
}

// ------------------------------------------------------------------ launch --
extern "C" void kernel_launch(void* const* d_in, const int* in_sizes, int n_in,
                              void* d_out, int out_size) {
    const float* vf      = (const float*)d_in[0];
    const int*   coords  = (const int*)  d_in[1];
    const int*   unq_inv = (const int*)  d_in[3];
    const int*   unq_cnt = (const int*)  d_in[4];
    const float* W1  = (const float*)d_in[5];
    const float* b1  = (const float*)d_in[6];
    const float* W2  = (const float*)d_in[7];
    const float* b2  = (const float*)d_in[8];
    const float* Wc1 = (const float*)d_in[9];
    const float* bc1 = (const float*)d_in[10];
    const float* Wc2 = (const float*)d_in[11];
    const float* bc2 = (const float*)d_in[12];
    const float* Wsp = (const float*)d_in[13];
    const float* bsp = (const float*)d_in[14];
    float* out = (float*)d_out;

    int N = in_sizes[0] / 5;
    if (N > NMAXV) N = NMAXV;
    int U = in_sizes[2];
    if (U > MAXU) U = MAXU;

    void* cnt_ptr = nullptr;
    cudaGetSymbolAddress(&cnt_ptr, g_cnt);
    cudaMemsetAsync(cnt_ptr, 0, (size_t)U * sizeof(int));

    scatter_kernel<<<(N + 255) / 256, 256>>>(unq_inv, coords, N);
    xemp_kernel<<<1, 64>>>(b1, W2, b2);
    mlp2_kernel<<<(N + 63) / 64, 256>>>(vf, W1, b1, W2, b2, N);
    pillar5_kernel<<<(U + 127) / 128, 128>>>(unq_cnt, Wc1, bc1, Wc2, bc2,
                                             Wsp, bsp, out, U);

    long long feat = (long long)U * 64;
    if ((long long)out_size > feat) {
        long long extra = (long long)out_size - feat;
        int n = (extra > U) ? U : (int)extra;
        mask_kernel<<<(n + 255) / 256, 256>>>(unq_cnt, out, feat, n);
    }
}

// round 10
// speedup vs baseline: 2.7900x; 2.7900x over previous
#include <cuda_runtime.h>
#include <cstdint>

#define NUM_BINS 32
#define MAXK     4
#define MAXU     100352
#define NMAXV    (2*MAXU)
#define NPAD     (NMAXV + 64)

typedef unsigned long long u64;

__device__ int   g_cnt[MAXU];
__device__ int4  g_list[MAXU];                   // packed (voxel<<5 | bin)
__device__ __align__(16) float g_xT[(size_t)64 * NPAD];  // transposed MLP out [c][v]
__device__ float g_xemp[64];                     // MLP(0) vector

// ---------------- packed f32x2 helpers -------------------------------------
__device__ __forceinline__ u64 pk2(float lo, float hi) {
    u64 r; asm("mov.b64 %0,{%1,%2};" : "=l"(r) : "f"(lo), "f"(hi)); return r;
}
__device__ __forceinline__ u64 dup2(float v) { return pk2(v, v); }
__device__ __forceinline__ void fma2(u64 &d, u64 a, u64 b) {
    asm("fma.rn.f32x2 %0,%1,%2,%0;" : "+l"(d) : "l"(a), "l"(b));
}
__device__ __forceinline__ u64 mul2(u64 a, u64 b) {
    u64 r; asm("mul.rn.f32x2 %0,%1,%2;" : "=l"(r) : "l"(a), "l"(b)); return r;
}
__device__ __forceinline__ u64 add2(u64 a, u64 b) {
    u64 r; asm("add.rn.f32x2 %0,%1,%2;" : "=l"(r) : "l"(a), "l"(b)); return r;
}
__device__ __forceinline__ float2 unpk(u64 v) {
    float2 r; asm("mov.b64 {%0,%1},%2;" : "=f"(r.x), "=f"(r.y) : "l"(v)); return r;
}
union F4U { float4 f; u64 u[2]; };

__device__ __forceinline__ float sigm(float x) {
    return __fdividef(1.f, 1.f + __expf(-x));
}

// ---------------------------------------------------------------- scatter ---
__global__ void scatter_kernel(const int* __restrict__ unq_inv,
                               const int* __restrict__ coords, int N) {
    int i = blockIdx.x * blockDim.x + threadIdx.x;
    if (i >= N) return;
    int p = unq_inv[i];
    int b = coords[4 * i + 1];
    int k = atomicAdd(&g_cnt[p], 1);
    if (k < MAXK) ((int*)g_list)[p * 4 + k] = (i << 5) | (b & 31);
}

// ------------------------------------------------------------------- mask ---
__global__ void mask_kernel(const int* __restrict__ cnt, float* __restrict__ out,
                            long long base, int n) {
    int i = blockIdx.x * blockDim.x + threadIdx.x;
    if (i < n) out[base + i] = (cnt[i] >= 2) ? 1.0f : 0.0f;
}

// ------------------------------------------------------------------- xemp ---
__global__ void xemp_kernel(const float* __restrict__ b1,
                            const float* __restrict__ W2,
                            const float* __restrict__ b2) {
    int c = threadIdx.x;   // 64 threads
    float acc = b2[c];
#pragma unroll
    for (int j = 0; j < 32; j++)
        acc = fmaf(fmaxf(b1[j], 0.f), W2[j * 64 + c], acc);
    g_xemp[c] = acc;
}

// ---------------------------------------------------- kernel A: MLP (tiled) --
__global__ __launch_bounds__(256)
void mlp2_kernel(const float* __restrict__ vf,
                 const float* __restrict__ W1, const float* __restrict__ b1,
                 const float* __restrict__ W2, const float* __restrict__ b2,
                 int N) {
    __shared__ __align__(16) float W1s[5][32];
    __shared__ __align__(16) float b1s[32];
    __shared__ __align__(16) float W2s[32][64];
    __shared__ __align__(16) float b2s[64];
    __shared__ __align__(16) float h_sh[32][68];
    __shared__ __align__(16) float x_sh[64][65];

    const int tid  = threadIdx.x;
    const int cp   = tid & 31;
    const int slot = tid >> 5;
    const int v0   = blockIdx.x * 64;

    for (int i = tid; i < 160; i += 256) W1s[i / 32][i % 32] = W1[i];
    if (tid < 32) b1s[tid] = b1[tid];
    for (int i = tid; i < 2048; i += 256) W2s[i >> 6][i & 63] = W2[i];
    if (tid < 64) b2s[tid] = b2[tid];
    __syncthreads();

    // ---- phase A: hidden ----
    {
        int v = tid & 63, qr = tid >> 6;
        int gv = v0 + v;
        float f[5];
        bool ok = gv < N;
#pragma unroll
        for (int i = 0; i < 5; i++) f[i] = ok ? vf[(size_t)gv * 5 + i] : 0.f;
        u64 acc[4];
#pragma unroll
        for (int t = 0; t < 4; t++) acc[t] = *(const u64*)&b1s[qr * 8 + 2 * t];
#pragma unroll
        for (int i = 0; i < 5; i++) {
            u64 fd = dup2(f[i]);
#pragma unroll
            for (int t = 0; t < 4; t++)
                fma2(acc[t], fd, *(const u64*)&W1s[i][qr * 8 + 2 * t]);
        }
#pragma unroll
        for (int t = 0; t < 4; t++) {
            float2 h = unpk(acc[t]);
            h_sh[qr * 8 + 2 * t][v]     = fmaxf(h.x, 0.f);
            h_sh[qr * 8 + 2 * t + 1][v] = fmaxf(h.y, 0.f);
        }
    }
    __syncthreads();

    // ---- phase B: layer 2 ----
    {
        const int vb = slot * 8;
        float2 b2p = *(const float2*)&b2s[2 * cp];
        u64 accA[4], accB[4];
#pragma unroll
        for (int t = 0; t < 4; t++) { accA[t] = dup2(b2p.x); accB[t] = dup2(b2p.y); }
#pragma unroll 4
        for (int j = 0; j < 32; j++) {
            F4U A, B;
            A.f = *(const float4*)&h_sh[j][vb];
            B.f = *(const float4*)&h_sh[j][vb + 4];
            float2 w = *(const float2*)&W2s[j][2 * cp];
            u64 d0 = dup2(w.x), d1 = dup2(w.y);
            fma2(accA[0], A.u[0], d0); fma2(accA[1], A.u[1], d0);
            fma2(accA[2], B.u[0], d0); fma2(accA[3], B.u[1], d0);
            fma2(accB[0], A.u[0], d1); fma2(accB[1], A.u[1], d1);
            fma2(accB[2], B.u[0], d1); fma2(accB[3], B.u[1], d1);
        }
#pragma unroll
        for (int t = 0; t < 4; t++) {
            float2 a = unpk(accA[t]);
            float2 b = unpk(accB[t]);
            x_sh[vb + 2 * t][2 * cp]         = a.x;
            x_sh[vb + 2 * t + 1][2 * cp]     = a.y;
            x_sh[vb + 2 * t][2 * cp + 1]     = b.x;
            x_sh[vb + 2 * t + 1][2 * cp + 1] = b.y;
        }
    }
    __syncthreads();

    for (int idx = tid; idx < 64 * 64; idx += 256) {
        int c = idx >> 6, v = idx & 63;
        if (v0 + v < N) g_xT[(size_t)c * NPAD + v0 + v] = x_sh[v][c];
    }
}

// -------------------------------------------------- kernel B: attention -----
// thread = pillar (pillar3 structure). Paired-voxel u64 fast path; quarter
// output staging; no register cap beyond the proven (128,5).
__global__ __launch_bounds__(128, 5)
void pillar6_kernel(const int* __restrict__ unq_cnt,
                    const float* __restrict__ Wc1, const float* __restrict__ bc1,
                    const float* __restrict__ Wc2, const float* __restrict__ bc2,
                    const float* __restrict__ Wsp, const float* __restrict__ bsp,
                    float* __restrict__ out, int U) {
    __shared__ __align__(16) float Wc1s[64 * 16];   // [c][j]
    __shared__ __align__(16) u64   Wc2P[32 * 16];   // [q][j] packed ch-pairs
    __shared__ __align__(16) float xemps[64];
    __shared__ __align__(16) u64   xem2[32];        // packed xemp pairs
    __shared__ float bc1s[16];
    __shared__ __align__(16) u64   bc22p[32];       // 2*bc2 packed pairs
    __shared__ __align__(16) u64   Amx[32];         // conv bg coeffs per bin
    __shared__ __align__(16) u64   wmx[7];          // packed (wm[t], wx[t])
    __shared__ __align__(16) u64   oh[8][131];      // quarter-output staging

    const int tid = threadIdx.x;
    for (int i = tid; i < 1024; i += 128) Wc1s[i] = Wc1[i];
    for (int i = tid; i < 512; i += 128) {
        int q = i >> 4, j = i & 15;
        Wc2P[q * 16 + j] = pk2(Wc2[j * 64 + 2 * q], Wc2[j * 64 + 2 * q + 1]);
    }
    if (tid < 64) xemps[tid] = g_xemp[tid];
    if (tid < 32) {
        xem2[tid]  = pk2(g_xemp[2 * tid], g_xemp[2 * tid + 1]);
        bc22p[tid] = pk2(2.f * bc2[2 * tid], 2.f * bc2[2 * tid + 1]);
        float am = 0.f, ax = 0.f;
#pragma unroll
        for (int t = 0; t < 7; t++) {
            int i2 = tid + t - 3;
            if (i2 >= 0 && i2 < 32) { am += Wsp[t]; ax += Wsp[7 + t]; }
        }
        Amx[tid] = pk2(am, ax);
    }
    if (tid < 16) bc1s[tid] = bc1[tid];
    if (tid < 7)  wmx[tid] = pk2(Wsp[tid], Wsp[7 + tid]);
    __syncthreads();

    const float bspv = bsp[0];
    const float NEG = __int_as_float(0xff800000);
    const int pbase = blockIdx.x * 128;
    const int p = pbase + tid;
    const bool active = p < U;

    int K = 0;
    int4 e = make_int4(0, 0, 0, 0);
    if (active) {
        K = unq_cnt[p];
        K = (K < 0) ? 0 : ((K > MAXK) ? MAXK : K);
        e = g_list[p];
    }
    int vs_[4] = { e.x >> 5, e.y >> 5, e.z >> 5, e.w >> 5 };
    int bs_[4] = { e.x & 31, e.y & 31, e.z & 31, e.w & 31 };
#pragma unroll
    for (int k = 0; k < 4; k++) if (k >= K) { bs_[k] = -1000; vs_[k] = 0; }
    const float fK = (float)(NUM_BINS - K);

    // Fast path: exactly 2 voxels, adjacent and 8B-aligned -> one LDG.64 each.
    const bool paired = (K == 2) && (vs_[1] == vs_[0] + 1) && ((vs_[0] & 1) == 0);
    const int vs0 = vs_[0];

    // ---- phase 1: avg/max per channel -> catt hidden partials -------------
    u64 ap[8], aq[8];
#pragma unroll
    for (int j = 0; j < 8; j++) { ap[j] = 0ull; aq[j] = 0ull; }
    if (paired) {
        const float* xc = g_xT;
#pragma unroll 4
        for (int c = 0; c < 64; c++) {
            float2 v = unpk(*(const u64*)(xc + vs0));
            float xe = xemps[c];
            float av = fmaf(30.f, xe, v.x + v.y) * 0.03125f;
            float mx = fmaxf(xe, fmaxf(v.x, v.y));
            u64 ad = dup2(av), md = dup2(mx);
            const ulonglong2* wr = (const ulonglong2*)&Wc1s[c * 16];
#pragma unroll
            for (int h = 0; h < 4; h++) {
                ulonglong2 w = wr[h];
                fma2(ap[2 * h],     ad, w.x);
                fma2(ap[2 * h + 1], ad, w.y);
                fma2(aq[2 * h],     md, w.x);
                fma2(aq[2 * h + 1], md, w.y);
            }
            xc += NPAD;
        }
    } else {
        const float* xc = g_xT;
#pragma unroll 4
        for (int c = 0; c < 64; c++) {
            float xe = xemps[c];
            float s = 0.f, mx = xe;
#pragma unroll
            for (int k = 0; k < 4; k++) if (k < K) {
                float xv = xc[vs_[k]];
                s += xv; mx = fmaxf(mx, xv);
            }
            float av = fmaf(fK, xe, s) * 0.03125f;
            u64 ad = dup2(av), md = dup2(mx);
            const ulonglong2* wr = (const ulonglong2*)&Wc1s[c * 16];
#pragma unroll
            for (int h = 0; h < 4; h++) {
                ulonglong2 w = wr[h];
                fma2(ap[2 * h],     ad, w.x);
                fma2(ap[2 * h + 1], ad, w.y);
                fma2(aq[2 * h],     md, w.x);
                fma2(aq[2 * h + 1], md, w.y);
            }
            xc += NPAD;
        }
    }

    // ---- catt gate vector, packed dups -----------------------------------
    u64 gd[16];
#pragma unroll
    for (int jp = 0; jp < 8; jp++) {
        float2 pp = unpk(ap[jp]);
        float2 qq = unpk(aq[jp]);
        float g0 = fmaxf(pp.x + bc1s[2 * jp], 0.f)     + fmaxf(qq.x + bc1s[2 * jp], 0.f);
        float g1 = fmaxf(pp.y + bc1s[2 * jp + 1], 0.f) + fmaxf(qq.y + bc1s[2 * jp + 1], 0.f);
        gd[2 * jp]     = dup2(g0);
        gd[2 * jp + 1] = dup2(g1);
    }

    // ---- phase 2: channel attention + bin statistics ---------------------
    float ssum[4] = {0.f, 0.f, 0.f, 0.f};
    float smax4[4] = {NEG, NEG, NEG, NEG};
    float sesum = 0.f, semax = NEG;
    if (paired) {
        const float* x0 = g_xT;
        const float* x1 = g_xT + NPAD;
        u64 ssum2 = 0ull;   // (ssum0, ssum1) packed over k
#pragma unroll 4
        for (int q = 0; q < 32; q++) {
            u64 acc = bc22p[q];
            const ulonglong2* w2 = (const ulonglong2*)&Wc2P[q * 16];
#pragma unroll
            for (int h = 0; h < 8; h++) {
                ulonglong2 w = w2[h];
                fma2(acc, gd[2 * h],     w.x);
                fma2(acc, gd[2 * h + 1], w.y);
            }
            float2 A = unpk(acc);
            float a0 = sigm(A.x), a1 = sigm(A.y);
            float2 xe = unpk(xem2[q]);
            float y0 = a0 * xe.x, y1 = a1 * xe.y;
            sesum += y0 + y1;
            semax = fmaxf(semax, fmaxf(y0, y1));
            u64 X0 = *(const u64*)(x0 + vs0);   // (x[2q][v0], x[2q][v1])
            u64 X1 = *(const u64*)(x1 + vs0);   // (x[2q+1][v0], x[2q+1][v1])
            u64 t0 = mul2(X0, dup2(a0));
            u64 t1 = mul2(X1, dup2(a1));
            ssum2 = add2(ssum2, add2(t0, t1));
            float2 f0 = unpk(t0), f1 = unpk(t1);
            smax4[0] = fmaxf(smax4[0], fmaxf(f0.x, f1.x));
            smax4[1] = fmaxf(smax4[1], fmaxf(f0.y, f1.y));
            x0 += 2 * NPAD;
            x1 += 2 * NPAD;
        }
        float2 sp = unpk(ssum2);
        ssum[0] = sp.x; ssum[1] = sp.y;
    } else {
        const float* x0 = g_xT;
        const float* x1 = g_xT + NPAD;
#pragma unroll 2
        for (int q = 0; q < 32; q++) {
            u64 acc = bc22p[q];
            const ulonglong2* w2 = (const ulonglong2*)&Wc2P[q * 16];
#pragma unroll
            for (int h = 0; h < 8; h++) {
                ulonglong2 w = w2[h];
                fma2(acc, gd[2 * h],     w.x);
                fma2(acc, gd[2 * h + 1], w.y);
            }
            float2 A = unpk(acc);
            float a0 = sigm(A.x), a1 = sigm(A.y);
            float2 xe = unpk(xem2[q]);
            float y0 = a0 * xe.x, y1 = a1 * xe.y;
            sesum += y0 + y1;
            semax = fmaxf(semax, fmaxf(y0, y1));
#pragma unroll
            for (int k = 0; k < 4; k++) if (k < K) {
                float z0 = a0 * x0[vs_[k]];
                float z1 = a1 * x1[vs_[k]];
                ssum[k] += z0 + z1;
                smax4[k] = fmaxf(smax4[k], fmaxf(z0, z1));
            }
            x0 += 2 * NPAD;
            x1 += 2 * NPAD;
        }
    }

    // ---- bin attention: bg + sparse corrections --------------------------
    const float se_m = sesum * (1.f / 64.f);
    const float se_x = semax;
    const u64 semx = pk2(se_m, se_x);
    u64 dk2[4];
#pragma unroll
    for (int k = 0; k < 4; k++)
        dk2[k] = pk2(ssum[k] * (1.f / 64.f) - se_m, smax4[k] - se_x);

    float argk[4] = {0.f, 0.f, 0.f, 0.f};
    float emax = NEG, emin = -NEG;
#pragma unroll
    for (int b = 0; b < 32; b++) {
        u64 a2 = pk2(bspv, 0.f);
        fma2(a2, semx, Amx[b]);
        bool occ = false;
        bool hit[4];
#pragma unroll
        for (int k = 0; k < 4; k++) {
            int d = bs_[k] - b;
            if ((unsigned)(d + 3) <= 6u) fma2(a2, dk2[k], wmx[d + 3]);
            hit[k] = (d == 0);
            occ |= hit[k];
        }
        float2 av = unpk(a2);
        float a = av.x + av.y;
#pragma unroll
        for (int k = 0; k < 4; k++) argk[k] = hit[k] ? a : argk[k];
        emax = occ ? emax : fmaxf(emax, a);
        emin = occ ? emin : fminf(emin, a);
    }
    float sigk[4];
#pragma unroll
    for (int k = 0; k < 4; k++) sigk[k] = sigm(argk[k]);
    const float sigeP = sigm(emax);    // y_empty >= 0
    const float sigeN = sigm(emin);    // y_empty <  0
    const u64 sk01 = pk2(sigk[0], sigk[1]);

    // ---- phase 3: final max over bins, 4 staged quarters -----------------
#pragma unroll
    for (int quarter = 0; quarter < 4; quarter++) {
        {
            const float* x0 = g_xT + (size_t)(quarter * 16) * NPAD;
            const float* x1 = x0 + NPAD;
#pragma unroll 2
            for (int qq = 0; qq < 8; qq++) {
                int q = quarter * 8 + qq;
                u64 acc = bc22p[q];
                const ulonglong2* w2 = (const ulonglong2*)&Wc2P[q * 16];
#pragma unroll
                for (int h = 0; h < 8; h++) {
                    ulonglong2 w = w2[h];
                    fma2(acc, gd[2 * h],     w.x);
                    fma2(acc, gd[2 * h + 1], w.y);
                }
                float2 A = unpk(acc);
                float a0 = sigm(A.x), a1 = sigm(A.y);
                float2 xe = unpk(xem2[q]);
                float M0 = xe.x * ((xe.x >= 0.f) ? sigeP : sigeN);
                float M1 = xe.y * ((xe.y >= 0.f) ? sigeP : sigeN);
                if (paired) {
                    float2 f0 = unpk(mul2(*(const u64*)(x0 + vs0), sk01));
                    float2 f1 = unpk(mul2(*(const u64*)(x1 + vs0), sk01));
                    M0 = fmaxf(M0, fmaxf(f0.x, f0.y));
                    M1 = fmaxf(M1, fmaxf(f1.x, f1.y));
                } else {
#pragma unroll
                    for (int k = 0; k < 4; k++) if (k < K) {
                        M0 = fmaxf(M0, x0[vs_[k]] * sigk[k]);
                        M1 = fmaxf(M1, x1[vs_[k]] * sigk[k]);
                    }
                }
                oh[qq][tid] = pk2(a0 * M0, a1 * M1);
                x0 += 2 * NPAD;
                x1 += 2 * NPAD;
            }
        }
        __syncthreads();
        for (int idx = tid; idx < 128 * 8; idx += 128) {
            int pl = idx >> 3, qq = idx & 7;
            int pg = pbase + pl;
            if (pg < U)
                *(u64*)(out + (size_t)pg * 64 + quarter * 16 + 2 * qq) = oh[qq][pl];
        }
        __syncthreads();
    }
}

// ------------------------------------------------------------------ launch --
extern "C" void kernel_launch(void* const* d_in, const int* in_sizes, int n_in,
                              void* d_out, int out_size) {
    const float* vf      = (const float*)d_in[0];
    const int*   coords  = (const int*)  d_in[1];
    const int*   unq_inv = (const int*)  d_in[3];
    const int*   unq_cnt = (const int*)  d_in[4];
    const float* W1  = (const float*)d_in[5];
    const float* b1  = (const float*)d_in[6];
    const float* W2  = (const float*)d_in[7];
    const float* b2  = (const float*)d_in[8];
    const float* Wc1 = (const float*)d_in[9];
    const float* bc1 = (const float*)d_in[10];
    const float* Wc2 = (const float*)d_in[11];
    const float* bc2 = (const float*)d_in[12];
    const float* Wsp = (const float*)d_in[13];
    const float* bsp = (const float*)d_in[14];
    float* out = (float*)d_out;

    int N = in_sizes[0] / 5;
    if (N > NMAXV) N = NMAXV;
    int U = in_sizes[2];
    if (U > MAXU) U = MAXU;

    void* cnt_ptr = nullptr;
    cudaGetSymbolAddress(&cnt_ptr, g_cnt);
    cudaMemsetAsync(cnt_ptr, 0, (size_t)U * sizeof(int));

    scatter_kernel<<<(N + 255) / 256, 256>>>(unq_inv, coords, N);
    xemp_kernel<<<1, 64>>>(b1, W2, b2);
    mlp2_kernel<<<(N + 63) / 64, 256>>>(vf, W1, b1, W2, b2, N);
    pillar6_kernel<<<(U + 127) / 128, 128>>>(unq_cnt, Wc1, bc1, Wc2, bc2,
                                             Wsp, bsp, out, U);

    long long feat = (long long)U * 64;
    if ((long long)out_size > feat) {
        long long extra = (long long)out_size - feat;
        int n = (extra > U) ? U : (int)extra;
        mask_kernel<<<(n + 255) / 256, 256>>>(unq_cnt, out, feat, n);
    }
}

// round 11
// speedup vs baseline: 4.0985x; 1.4690x over previous
#include <cuda_runtime.h>
#include <cstdint>

#define NUM_BINS 32
#define MAXK     4
#define MAXU     100352
#define NMAXV    (2*MAXU)
#define NPAD     (NMAXV + 64)

typedef unsigned long long u64;

__device__ int   g_cnt[MAXU];
__device__ int4  g_list[MAXU];                   // packed (voxel<<5 | bin)
__device__ float g_xT[(size_t)64 * NPAD];        // transposed MLP output [c][v]
__device__ float g_xemp[64];                     // MLP(0) vector

// ---------------- packed f32x2 helpers -------------------------------------
__device__ __forceinline__ u64 pk2(float lo, float hi) {
    u64 r; asm("mov.b64 %0,{%1,%2};" : "=l"(r) : "f"(lo), "f"(hi)); return r;
}
__device__ __forceinline__ u64 dup2(float v) { return pk2(v, v); }
__device__ __forceinline__ void fma2(u64 &d, u64 a, u64 b) {
    asm("fma.rn.f32x2 %0,%1,%2,%0;" : "+l"(d) : "l"(a), "l"(b));
}
__device__ __forceinline__ float2 unpk(u64 v) {
    float2 r; asm("mov.b64 {%0,%1},%2;" : "=f"(r.x), "=f"(r.y) : "l"(v)); return r;
}
union F4U { float4 f; u64 u[2]; };

__device__ __forceinline__ float sigm(float x) {
    return __fdividef(1.f, 1.f + __expf(-x));
}

// ---------------------------------------------------------------- scatter ---
__global__ void scatter_kernel(const int* __restrict__ unq_inv,
                               const int* __restrict__ coords, int N) {
    int i = blockIdx.x * blockDim.x + threadIdx.x;
    if (i >= N) return;
    int p = unq_inv[i];
    int b = coords[4 * i + 1];
    int k = atomicAdd(&g_cnt[p], 1);
    if (k < MAXK) ((int*)g_list)[p * 4 + k] = (i << 5) | (b & 31);
}

// ------------------------------------------------------------------- mask ---
__global__ void mask_kernel(const int* __restrict__ cnt, float* __restrict__ out,
                            long long base, int n) {
    int i = blockIdx.x * blockDim.x + threadIdx.x;
    if (i < n) out[base + i] = (cnt[i] >= 2) ? 1.0f : 0.0f;
}

// ------------------------------------------------------------------- xemp ---
__global__ void xemp_kernel(const float* __restrict__ b1,
                            const float* __restrict__ W2,
                            const float* __restrict__ b2) {
    int c = threadIdx.x;   // 64 threads
    float acc = b2[c];
#pragma unroll
    for (int j = 0; j < 32; j++)
        acc = fmaf(fmaxf(b1[j], 0.f), W2[j * 64 + c], acc);
    g_xemp[c] = acc;
}

// ---------------------------------------------------- kernel A: MLP (tiled) --
__global__ __launch_bounds__(256)
void mlp2_kernel(const float* __restrict__ vf,
                 const float* __restrict__ W1, const float* __restrict__ b1,
                 const float* __restrict__ W2, const float* __restrict__ b2,
                 int N) {
    __shared__ __align__(16) float W1s[5][32];
    __shared__ __align__(16) float b1s[32];
    __shared__ __align__(16) float W2s[32][64];
    __shared__ __align__(16) float b2s[64];
    __shared__ __align__(16) float h_sh[32][68];
    __shared__ __align__(16) float x_sh[64][65];

    const int tid  = threadIdx.x;
    const int cp   = tid & 31;
    const int slot = tid >> 5;
    const int v0   = blockIdx.x * 64;

    for (int i = tid; i < 160; i += 256) W1s[i / 32][i % 32] = W1[i];
    if (tid < 32) b1s[tid] = b1[tid];
    for (int i = tid; i < 2048; i += 256) W2s[i >> 6][i & 63] = W2[i];
    if (tid < 64) b2s[tid] = b2[tid];
    __syncthreads();

    // ---- phase A: hidden ----
    {
        int v = tid & 63, qr = tid >> 6;
        int gv = v0 + v;
        float f[5];
        bool ok = gv < N;
#pragma unroll
        for (int i = 0; i < 5; i++) f[i] = ok ? vf[(size_t)gv * 5 + i] : 0.f;
        u64 acc[4];
#pragma unroll
        for (int t = 0; t < 4; t++) acc[t] = *(const u64*)&b1s[qr * 8 + 2 * t];
#pragma unroll
        for (int i = 0; i < 5; i++) {
            u64 fd = dup2(f[i]);
#pragma unroll
            for (int t = 0; t < 4; t++)
                fma2(acc[t], fd, *(const u64*)&W1s[i][qr * 8 + 2 * t]);
        }
#pragma unroll
        for (int t = 0; t < 4; t++) {
            float2 h = unpk(acc[t]);
            h_sh[qr * 8 + 2 * t][v]     = fmaxf(h.x, 0.f);
            h_sh[qr * 8 + 2 * t + 1][v] = fmaxf(h.y, 0.f);
        }
    }
    __syncthreads();

    // ---- phase B: layer 2 ----
    {
        const int vb = slot * 8;
        float2 b2p = *(const float2*)&b2s[2 * cp];
        u64 accA[4], accB[4];
#pragma unroll
        for (int t = 0; t < 4; t++) { accA[t] = dup2(b2p.x); accB[t] = dup2(b2p.y); }
#pragma unroll 4
        for (int j = 0; j < 32; j++) {
            F4U A, B;
            A.f = *(const float4*)&h_sh[j][vb];
            B.f = *(const float4*)&h_sh[j][vb + 4];
            float2 w = *(const float2*)&W2s[j][2 * cp];
            u64 d0 = dup2(w.x), d1 = dup2(w.y);
            fma2(accA[0], A.u[0], d0); fma2(accA[1], A.u[1], d0);
            fma2(accA[2], B.u[0], d0); fma2(accA[3], B.u[1], d0);
            fma2(accB[0], A.u[0], d1); fma2(accB[1], A.u[1], d1);
            fma2(accB[2], B.u[0], d1); fma2(accB[3], B.u[1], d1);
        }
#pragma unroll
        for (int t = 0; t < 4; t++) {
            float2 a = unpk(accA[t]);
            float2 b = unpk(accB[t]);
            x_sh[vb + 2 * t][2 * cp]         = a.x;
            x_sh[vb + 2 * t + 1][2 * cp]     = a.y;
            x_sh[vb + 2 * t][2 * cp + 1]     = b.x;
            x_sh[vb + 2 * t + 1][2 * cp + 1] = b.y;
        }
    }
    __syncthreads();

    for (int idx = tid; idx < 64 * 64; idx += 256) {
        int c = idx >> 6, v = idx & 63;
        if (v0 + v < N) g_xT[(size_t)c * NPAD + v0 + v] = x_sh[v][c];
    }
}

// -------------------------------------------------- kernel B: attention -----
// thread = pillar; EXACT pillar3 (R6, 68us) structure. Deltas: upper-half att
// cached in oh during phase 2 (phase 3 half-1 reads it instead of recomputing
// the Wc2 matvec), u64 writeout, packed xemp reads.
__global__ __launch_bounds__(128, 5)
void pillar7_kernel(const int* __restrict__ unq_cnt,
                    const float* __restrict__ Wc1, const float* __restrict__ bc1,
                    const float* __restrict__ Wc2, const float* __restrict__ bc2,
                    const float* __restrict__ Wsp, const float* __restrict__ bsp,
                    float* __restrict__ out, int U) {
    __shared__ __align__(16) float Wc1s[64 * 16];   // [c][j]
    __shared__ __align__(16) u64   Wc2P[32 * 16];   // [q][j] packed ch-pairs
    __shared__ __align__(16) float xemps[64];
    __shared__ __align__(16) u64   xem2[32];        // packed xemp pairs
    __shared__ float bc1s[16];
    __shared__ __align__(16) u64   bc22p[32];       // 2*bc2 packed pairs
    __shared__ __align__(16) u64   Amx[32];         // conv bg coeffs per bin
    __shared__ __align__(16) u64   wmx[8];          // packed (wm[t], wx[t])
    __shared__ __align__(16) u64   oh[16][131];     // att cache / out staging

    const int tid = threadIdx.x;
    for (int i = tid; i < 1024; i += 128) Wc1s[i] = Wc1[i];
    for (int i = tid; i < 512; i += 128) {
        int q = i >> 4, j = i & 15;
        Wc2P[q * 16 + j] = pk2(Wc2[j * 64 + 2 * q], Wc2[j * 64 + 2 * q + 1]);
    }
    if (tid < 64) xemps[tid] = g_xemp[tid];
    if (tid < 32) {
        xem2[tid]  = pk2(g_xemp[2 * tid], g_xemp[2 * tid + 1]);
        bc22p[tid] = pk2(2.f * bc2[2 * tid], 2.f * bc2[2 * tid + 1]);
        float am = 0.f, ax = 0.f;
#pragma unroll
        for (int t = 0; t < 7; t++) {
            int i2 = tid + t - 3;
            if (i2 >= 0 && i2 < 32) { am += Wsp[t]; ax += Wsp[7 + t]; }
        }
        Amx[tid] = pk2(am, ax);
    }
    if (tid < 16) bc1s[tid] = bc1[tid];
    if (tid < 7)  wmx[tid] = pk2(Wsp[tid], Wsp[7 + tid]);
    __syncthreads();

    const float bspv = bsp[0];
    const float NEG = __int_as_float(0xff800000);
    const int pbase = blockIdx.x * 128;
    const int p = pbase + tid;
    const bool active = p < U;

    int K = 0;
    int4 e = make_int4(0, 0, 0, 0);
    if (active) {
        K = unq_cnt[p];
        K = (K < 0) ? 0 : ((K > MAXK) ? MAXK : K);
        e = g_list[p];
    }
    int vs_[4] = { e.x >> 5, e.y >> 5, e.z >> 5, e.w >> 5 };
    int bs_[4] = { e.x & 31, e.y & 31, e.z & 31, e.w & 31 };
#pragma unroll
    for (int k = 0; k < 4; k++) if (k >= K) { bs_[k] = -1000; vs_[k] = 0; }
    const float fK = (float)(NUM_BINS - K);

    // ---- phase 1: avg/max per channel -> catt hidden partials -------------
    u64 ap[8], aq[8];
#pragma unroll
    for (int j = 0; j < 8; j++) { ap[j] = 0ull; aq[j] = 0ull; }
    {
        const float* xc = g_xT;
#pragma unroll 4
        for (int c = 0; c < 64; c++) {
            float xe = xemps[c];
            float s = 0.f, mx = xe;
#pragma unroll
            for (int k = 0; k < 4; k++) if (k < K) {
                float xv = xc[vs_[k]];
                s += xv; mx = fmaxf(mx, xv);
            }
            float av = (s + fK * xe) * 0.03125f;
            u64 ad = dup2(av), md = dup2(mx);
            const ulonglong2* wr = (const ulonglong2*)&Wc1s[c * 16];
#pragma unroll
            for (int h = 0; h < 4; h++) {
                ulonglong2 w = wr[h];
                fma2(ap[2 * h],     ad, w.x);
                fma2(ap[2 * h + 1], ad, w.y);
                fma2(aq[2 * h],     md, w.x);
                fma2(aq[2 * h + 1], md, w.y);
            }
            xc += NPAD;
        }
    }

    // ---- catt gate vector, packed dups -----------------------------------
    u64 gd[16];
#pragma unroll
    for (int jp = 0; jp < 8; jp++) {
        float2 pp = unpk(ap[jp]);
        float2 qq = unpk(aq[jp]);
        float g0 = fmaxf(pp.x + bc1s[2 * jp], 0.f)     + fmaxf(qq.x + bc1s[2 * jp], 0.f);
        float g1 = fmaxf(pp.y + bc1s[2 * jp + 1], 0.f) + fmaxf(qq.y + bc1s[2 * jp + 1], 0.f);
        gd[2 * jp]     = dup2(g0);
        gd[2 * jp + 1] = dup2(g1);
    }

    // ---- phase 2: channel attention + bin statistics ---------------------
    // Lower 16 q: compute only. Upper 16 q: also cache att in oh[q-16][tid].
    float ssum[4] = {0.f, 0.f, 0.f, 0.f};
    float smax4[4] = {NEG, NEG, NEG, NEG};
    float sesum = 0.f, semax = NEG;
    {
        const float* x0 = g_xT;
        const float* x1 = g_xT + NPAD;
#pragma unroll 2
        for (int q = 0; q < 16; q++) {
            u64 acc = bc22p[q];
            const ulonglong2* w2 = (const ulonglong2*)&Wc2P[q * 16];
#pragma unroll
            for (int h = 0; h < 8; h++) {
                ulonglong2 w = w2[h];
                fma2(acc, gd[2 * h],     w.x);
                fma2(acc, gd[2 * h + 1], w.y);
            }
            float2 A = unpk(acc);
            float a0 = sigm(A.x), a1 = sigm(A.y);
            float2 xe = unpk(xem2[q]);
            float y0 = a0 * xe.x, y1 = a1 * xe.y;
            sesum += y0 + y1;
            semax = fmaxf(semax, fmaxf(y0, y1));
#pragma unroll
            for (int k = 0; k < 4; k++) if (k < K) {
                float z0 = a0 * x0[vs_[k]];
                float z1 = a1 * x1[vs_[k]];
                ssum[k] += z0 + z1;
                smax4[k] = fmaxf(smax4[k], fmaxf(z0, z1));
            }
            x0 += 2 * NPAD;
            x1 += 2 * NPAD;
        }
#pragma unroll 2
        for (int q = 16; q < 32; q++) {
            u64 acc = bc22p[q];
            const ulonglong2* w2 = (const ulonglong2*)&Wc2P[q * 16];
#pragma unroll
            for (int h = 0; h < 8; h++) {
                ulonglong2 w = w2[h];
                fma2(acc, gd[2 * h],     w.x);
                fma2(acc, gd[2 * h + 1], w.y);
            }
            float2 A = unpk(acc);
            float a0 = sigm(A.x), a1 = sigm(A.y);
            oh[q - 16][tid] = pk2(a0, a1);       // cache att for phase 3
            float2 xe = unpk(xem2[q]);
            float y0 = a0 * xe.x, y1 = a1 * xe.y;
            sesum += y0 + y1;
            semax = fmaxf(semax, fmaxf(y0, y1));
#pragma unroll
            for (int k = 0; k < 4; k++) if (k < K) {
                float z0 = a0 * x0[vs_[k]];
                float z1 = a1 * x1[vs_[k]];
                ssum[k] += z0 + z1;
                smax4[k] = fmaxf(smax4[k], fmaxf(z0, z1));
            }
            x0 += 2 * NPAD;
            x1 += 2 * NPAD;
        }
    }

    // ---- bin attention: bg + sparse corrections --------------------------
    const float se_m = sesum * (1.f / 64.f);
    const float se_x = semax;
    const u64 semx = pk2(se_m, se_x);
    u64 dk2[4];
#pragma unroll
    for (int k = 0; k < 4; k++)
        dk2[k] = pk2(ssum[k] * (1.f / 64.f) - se_m, smax4[k] - se_x);

    float argk[4] = {0.f, 0.f, 0.f, 0.f};
    float emax = NEG, emin = -NEG;
#pragma unroll
    for (int b = 0; b < 32; b++) {
        u64 a2 = pk2(bspv, 0.f);
        fma2(a2, semx, Amx[b]);
        bool occ = false;
        bool hit[4];
#pragma unroll
        for (int k = 0; k < 4; k++) {
            int d = bs_[k] - b;
            if ((unsigned)(d + 3) <= 6u) fma2(a2, dk2[k], wmx[d + 3]);
            hit[k] = (d == 0);
            occ |= hit[k];
        }
        float2 av = unpk(a2);
        float a = av.x + av.y;
#pragma unroll
        for (int k = 0; k < 4; k++) argk[k] = hit[k] ? a : argk[k];
        emax = occ ? emax : fmaxf(emax, a);
        emin = occ ? emin : fminf(emin, a);
    }
    float sigk[4];
#pragma unroll
    for (int k = 0; k < 4; k++) sigk[k] = sigm(argk[k]);
    const float sigeP = sigm(emax);    // y_empty >= 0
    const float sigeN = sigm(emin);    // y_empty <  0

    // ---- phase 3, half 1 FIRST (channels 32..63): att cached in oh -------
    {
        const float* x0 = g_xT + (size_t)32 * NPAD;
        const float* x1 = x0 + NPAD;
#pragma unroll 2
        for (int qq = 0; qq < 16; qq++) {
            int q = 16 + qq;
            float2 A = unpk(oh[qq][tid]);        // own column: no sync hazard
            float2 xe = unpk(xem2[q]);
            float M0 = xe.x * ((xe.x >= 0.f) ? sigeP : sigeN);
            float M1 = xe.y * ((xe.y >= 0.f) ? sigeP : sigeN);
#pragma unroll
            for (int k = 0; k < 4; k++) if (k < K) {
                M0 = fmaxf(M0, x0[vs_[k]] * sigk[k]);
                M1 = fmaxf(M1, x1[vs_[k]] * sigk[k]);
            }
            oh[qq][tid] = pk2(A.x * M0, A.y * M1);
            x0 += 2 * NPAD;
            x1 += 2 * NPAD;
        }
    }
    __syncthreads();
    for (int idx = tid; idx < 128 * 16; idx += 128) {
        int pl = idx >> 4, qq = idx & 15;
        int pg = pbase + pl;
        if (pg < U)
            *(u64*)(out + (size_t)pg * 64 + 32 + 2 * qq) = oh[qq][pl];
    }
    __syncthreads();

    // ---- phase 3, half 0 (channels 0..31): recompute att matvec ----------
    {
        const float* x0 = g_xT;
        const float* x1 = g_xT + NPAD;
#pragma unroll 2
        for (int q = 0; q < 16; q++) {
            u64 acc = bc22p[q];
            const ulonglong2* w2 = (const ulonglong2*)&Wc2P[q * 16];
#pragma unroll
            for (int h = 0; h < 8; h++) {
                ulonglong2 w = w2[h];
                fma2(acc, gd[2 * h],     w.x);
                fma2(acc, gd[2 * h + 1], w.y);
            }
            float2 A = unpk(acc);
            float a0 = sigm(A.x), a1 = sigm(A.y);
            float2 xe = unpk(xem2[q]);
            float M0 = xe.x * ((xe.x >= 0.f) ? sigeP : sigeN);
            float M1 = xe.y * ((xe.y >= 0.f) ? sigeP : sigeN);
#pragma unroll
            for (int k = 0; k < 4; k++) if (k < K) {
                M0 = fmaxf(M0, x0[vs_[k]] * sigk[k]);
                M1 = fmaxf(M1, x1[vs_[k]] * sigk[k]);
            }
            oh[q][tid] = pk2(a0 * M0, a1 * M1);
            x0 += 2 * NPAD;
            x1 += 2 * NPAD;
        }
    }
    __syncthreads();
    for (int idx = tid; idx < 128 * 16; idx += 128) {
        int pl = idx >> 4, qq = idx & 15;
        int pg = pbase + pl;
        if (pg < U)
            *(u64*)(out + (size_t)pg * 64 + 2 * qq) = oh[qq][pl];
    }
}

// ------------------------------------------------------------------ launch --
extern "C" void kernel_launch(void* const* d_in, const int* in_sizes, int n_in,
                              void* d_out, int out_size) {
    const float* vf      = (const float*)d_in[0];
    const int*   coords  = (const int*)  d_in[1];
    const int*   unq_inv = (const int*)  d_in[3];
    const int*   unq_cnt = (const int*)  d_in[4];
    const float* W1  = (const float*)d_in[5];
    const float* b1  = (const float*)d_in[6];
    const float* W2  = (const float*)d_in[7];
    const float* b2  = (const float*)d_in[8];
    const float* Wc1 = (const float*)d_in[9];
    const float* bc1 = (const float*)d_in[10];
    const float* Wc2 = (const float*)d_in[11];
    const float* bc2 = (const float*)d_in[12];
    const float* Wsp = (const float*)d_in[13];
    const float* bsp = (const float*)d_in[14];
    float* out = (float*)d_out;

    int N = in_sizes[0] / 5;
    if (N > NMAXV) N = NMAXV;
    int U = in_sizes[2];
    if (U > MAXU) U = MAXU;

    void* cnt_ptr = nullptr;
    cudaGetSymbolAddress(&cnt_ptr, g_cnt);
    cudaMemsetAsync(cnt_ptr, 0, (size_t)U * sizeof(int));

    scatter_kernel<<<(N + 255) / 256, 256>>>(unq_inv, coords, N);
    xemp_kernel<<<1, 64>>>(b1, W2, b2);
    mlp2_kernel<<<(N + 63) / 64, 256>>>(vf, W1, b1, W2, b2, N);
    pillar7_kernel<<<(U + 127) / 128, 128>>>(unq_cnt, Wc1, bc1, Wc2, bc2,
                                             Wsp, bsp, out, U);

    long long feat = (long long)U * 64;
    if ((long long)out_size > feat) {
        long long extra = (long long)out_size - feat;
        int n = (extra > U) ? U : (int)extra;
        mask_kernel<<<(n + 255) / 256, 256>>>(unq_cnt, out, feat, n);
    }
}